// round 9
// baseline (speedup 1.0000x reference)
#include <cuda_runtime.h>
#include <cuda_fp16.h>
#include <cstdint>
#include <math.h>

#define Bn 256
#define Tn 4096
#define BT (Bn*Tn)

__device__ unsigned g_h [BT];   // GRU hidden half2
__device__ float    g_gm[BT];   // gamma_1

static __device__ __forceinline__ __half2 tanh2(__half2 x){
    unsigned xi = *reinterpret_cast<unsigned*>(&x), ri;
    asm("tanh.approx.f16x2 %0, %1;" : "=r"(ri) : "r"(xi));
    return *reinterpret_cast<__half2*>(&ri);
}
static __device__ __forceinline__ float tanhap(float x){
    float y; asm("tanh.approx.f32 %0, %1;" : "=f"(y) : "f"(x)); return y;
}

// ============== K1: GRU — staged gates, 2 sections/batch, 256 thr ==============
// grid 512: block = (batch, section of 2048 t). 256 threads stage; 128 run chains.
#define G_GATE 6336                 // words: 2064*3 + pads
#define G_HB   2304                 // words: 2048 + pads
#define GRU_SMEM ((G_GATE+G_HB)*4)  // 34560 B

__global__ __launch_bounds__(256) void gru_kernel(
    const float* __restrict__ x,
    const float* __restrict__ wih, const float* __restrict__ whh,
    const float* __restrict__ bih, const float* __restrict__ bhh)
{
    extern __shared__ unsigned sg[];
    unsigned* gbuf = sg;
    unsigned* hbuf = sg + G_GATE;

    int b   = blockIdx.x >> 1;
    int sec = blockIdx.x & 1;
    int tid = threadIdx.x;

    int off      = sec ? 16 : 0;             // warmup prefix length in tile
    int tbase    = sec*2048 - off;           // global t of tile[0]
    int tile_len = 2048 + off;

    // weights (r,z pre-halved, biases folded)
    float WI[18], CB[6];
#pragma unroll
    for (int j=0;j<4;j++){
#pragma unroll
        for (int d=0;d<3;d++) WI[j*3+d] = 0.5f*wih[j*3+d];
        CB[j] = 0.5f*(bih[j]+bhh[j]);
    }
#pragma unroll
    for (int j=4;j<6;j++){
#pragma unroll
        for (int d=0;d<3;d++) WI[j*3+d] = wih[j*3+d];
        CB[j] = bih[j];
    }
    float w[12];
#pragma unroll
    for (int i=0;i<12;i++) w[i]=whh[i];
    __half2 WRA=__floats2half2_rn(0.5f*w[0],0.5f*w[2]), WRB=__floats2half2_rn(0.5f*w[1],0.5f*w[3]);
    __half2 WZA=__floats2half2_rn(0.5f*w[4],0.5f*w[6]), WZB=__floats2half2_rn(0.5f*w[5],0.5f*w[7]);
    __half2 WNA=__floats2half2_rn(w[8],w[10]),          WNB=__floats2half2_rn(w[9],w[11]);
    __half2 BN =__floats2half2_rn(bhh[4],bhh[5]);
    const __half2 H05=__floats2half2_rn(0.5f,0.5f), HM05=__floats2half2_rn(-0.5f,-0.5f);

    // ---- stage gates (off-chain, all 256 threads, coalesced-ish 12B/lane) ----
    const float* xb = x + (size_t)(b*Tn + tbase)*3;
    for (int k=tid; k<tile_len; k+=256){
        float x0=xb[k*3], x1=xb[k*3+1], x2=xb[k*3+2];
        float gr0=fmaf(WI[0],x0,fmaf(WI[1],x1,fmaf(WI[2],x2,CB[0])));
        float gr1=fmaf(WI[3],x0,fmaf(WI[4],x1,fmaf(WI[5],x2,CB[1])));
        float gz0=fmaf(WI[6],x0,fmaf(WI[7],x1,fmaf(WI[8],x2,CB[2])));
        float gz1=fmaf(WI[9],x0,fmaf(WI[10],x1,fmaf(WI[11],x2,CB[3])));
        float gn0=fmaf(WI[12],x0,fmaf(WI[13],x1,fmaf(WI[14],x2,CB[4])));
        float gn1=fmaf(WI[15],x0,fmaf(WI[16],x1,fmaf(WI[17],x2,CB[5])));
        __half2 CR=__floats2half2_rn(gr0,gr1);
        __half2 CZ=__floats2half2_rn(gz0,gz1);
        __half2 CN=__floats2half2_rn(gn0,gn1);
        int a = k*3 + (k>>4);
        gbuf[a]   = *reinterpret_cast<unsigned*>(&CR);
        gbuf[a+1] = *reinterpret_cast<unsigned*>(&CZ);
        gbuf[a+2] = *reinterpret_cast<unsigned*>(&CN);
    }
    __syncthreads();

    // ---- serial chain: 128 chunks of 16 (16-step warmup), lean loop ----
    if (tid < 128) {
        int c = tid;
        int li = (sec==0 && c==0) ? 0 : (off + c*16 - 16);
        int nwarm = (sec==0 && c==0) ? 0 : 16;

        __half2 h = __floats2half2_rn(0.f,0.f);
#pragma unroll 4
        for (int s=0; s<32; s++){
            int tt = li + s;
            int a  = tt*3 + (tt>>4);
            unsigned u0=gbuf[a], u1=gbuf[a+1], u2=gbuf[a+2];
            __half2 CR=*reinterpret_cast<__half2*>(&u0);
            __half2 CZ=*reinterpret_cast<__half2*>(&u1);
            __half2 CN=*reinterpret_cast<__half2*>(&u2);

            __half2 h0b=__half2half2(__low2half(h)), h1b=__half2half2(__high2half(h));
            __half2 aR=__hfma2(h0b,WRA,__hfma2(h1b,WRB,CR));
            __half2 aZ=__hfma2(h0b,WZA,__hfma2(h1b,WZB,CZ));
            __half2 GN=__hfma2(h0b,WNA,__hfma2(h1b,WNB,BN));
            __half2 tr=tanh2(aR), tz=tanh2(aZ);
            __half2 Ch=__hmul2(GN,H05);
            __half2 aN=__hfma2(tr,Ch,__hadd2(CN,Ch));
            __half2 tn=tanh2(aN);
            __half2 A =__hfma2(tz,HM05,H05);
            __half2 hh=__hmul2(h,H05);
            __half2 ZH=__hfma2(tz,hh,hh);
            h = __hfma2(tn,A,ZH);

            if (s>=nwarm && s<nwarm+16){
                int o = tt - off;
                hbuf[o + (o>>4)] = *reinterpret_cast<unsigned*>(&h);
            }
        }
    }
    __syncthreads();

    // ---- coalesced writeback ----
    unsigned* hout = g_h + (size_t)b*Tn + sec*2048;
#pragma unroll
    for (int u=tid; u<2048; u+=256) hout[u] = hbuf[u + (u>>4)];
}

// ============== K2: emitter + HMM scan -> gamma1 ==============
#define TP(t) ((t) + ((t)>>4))
#define HSQ   0
#define HSUF  4352
#define HSVF  8704
#define HSXE  13056
#define HSSUB 16128
#define HSP   17152
#define HSBF  17664
#define HSEB  17920
#define HMM_SMEM (18176*4)

__global__ __launch_bounds__(256) void hmm_kernel(
    const float* __restrict__ x,
    const float* __restrict__ lpi, const float* __restrict__ lAg,
    const float* __restrict__ fc1w,const float* __restrict__ fc1b,
    const float* __restrict__ fc2w,const float* __restrict__ fc2b)
{
    extern __shared__ float sm[];
    float* sq   = sm + HSQ;
    float* suf  = sm + HSUF;
    float* svf  = sm + HSVF;
    float* sxe  = sm + HSXE;
    float* sSub = sm + HSSUB;
    float* sP   = sm + HSP;
    float* sBf  = sm + HSBF;
    float* sEb  = sm + HSEB;

    int b = blockIdx.x, tid = threadIdx.x;

    float W1[24], B1[8], DW[8];
#pragma unroll
    for (int i=0;i<24;i++) W1[i]=fc1w[i];
#pragma unroll
    for (int i=0;i<8;i++){ B1[i]=fc1b[i]; DW[i]=fc2w[8+i]-fc2w[i]; }
    float db = fc2b[1]-fc2b[0];

    for (int sec=0; sec<4; sec++){
        const float* xb = x + ((size_t)b*Tn + sec*1024)*3;
        __syncthreads();
#pragma unroll
        for (int i=tid;i<3072;i+=256) sxe[i]=xb[i];
        __syncthreads();
#pragma unroll
        for (int j=0;j<4;j++){
            int tl = tid + j*256;
            float x0=sxe[tl*3], x1=sxe[tl*3+1], x2=sxe[tl*3+2];
            float d = db;
#pragma unroll
            for (int k=0;k<8;k++){
                float u = fmaf(W1[k*3],x0,fmaf(W1[k*3+1],x1,fmaf(W1[k*3+2],x2,B1[k])));
                d = fmaf(DW[k], tanhap(u), d);
            }
            int t = sec*1024 + tl;
            sq[TP(t)] = __expf(d);
        }
    }

    float l00=lAg[0],l01=lAg[1],l10=lAg[2],l11=lAg[3];
    float m0=fmaxf(l00,l01), m1=fmaxf(l10,l11);
    float e00=__expf(l00-m0), e01=__expf(l01-m0), e10=__expf(l10-m1), e11=__expf(l11-m1);
    float i0=__fdividef(1.f,e00+e01), i1=__fdividef(1.f,e10+e11);
    float a00=e00*i0, a01=e01*i0, a10=e10*i1, a11=e11*i1;
    float p1=__expf(lpi[1]-lpi[0]);
    __syncthreads();

    // 16-step sub-products
    {
        int ts = tid*16, te = ts+16;
        if (tid==0) ts = 1;
        float p00=1.f,p01=0.f,p10=0.f,p11=1.f;
        for (int t=ts;t<te;t++){
            float qv=sq[TP(t)], qa01=a01*qv, qa11=a11*qv;
            float n00=fmaf(p01,a10,p00*a00), n01=fmaf(p01,qa11,p00*qa01);
            float n10=fmaf(p11,a10,p10*a00), n11=fmaf(p11,qa11,p10*qa01);
            p00=n00;p01=n01;p10=n10;p11=n11;
        }
        float s=__fdividef(1.f,p00+p01+p10+p11);
        sSub[tid*4]=p00*s; sSub[tid*4+1]=p01*s; sSub[tid*4+2]=p10*s; sSub[tid*4+3]=p11*s;
    }
    __syncthreads();

    // combine -> 128 chunk products (32 t each)
    if (tid < 128) {
        const float* S0 = sSub + tid*8;
        const float* S1 = S0 + 4;
        float p00=S0[0],p01=S0[1],p10=S0[2],p11=S0[3];
        float n00=fmaf(p01,S1[2],p00*S1[0]), n01=fmaf(p01,S1[3],p00*S1[1]);
        float n10=fmaf(p11,S1[2],p10*S1[0]), n11=fmaf(p11,S1[3],p10*S1[1]);
        float s=__fdividef(1.f,n00+n01+n10+n11);
        sP[tid*4]=n00*s; sP[tid*4+1]=n01*s; sP[tid*4+2]=n10*s; sP[tid*4+3]=n11*s;
    }
    __syncthreads();

    // boundary chains
    if (tid == 0) {
        float u=1.f, v=p1*sq[TP(0)];
        sBf[0]=u; sBf[1]=v;
        for (int c=0;c<127;c++){
            const float* P=sP+c*4;
            float nu=fmaf(v,P[2],u*P[0]);
            float nv=fmaf(v,P[3],u*P[1]);
            u=nu; v=nv;
            if ((c&7)==7){ float is=__fdividef(1.f,u+v); u*=is; v*=is; }
            sBf[(c+1)*2]=u; sBf[(c+1)*2+1]=v;
        }
    } else if (tid == 32) {
        float u=1.f, v=1.f;
        sEb[127*2]=1.f; sEb[127*2+1]=1.f;
        for (int c=126;c>=0;c--){
            const float* P=sP+(c+1)*4;
            float nu=fmaf(P[1],v,P[0]*u);
            float nv=fmaf(P[3],v,P[2]*u);
            u=nu; v=nv;
            if ((c&7)==0){ float is=__fdividef(1.f,u+v); u*=is; v*=is; }
            sEb[c*2]=u; sEb[c*2+1]=v;
        }
    }
    __syncthreads();

    // forward replay
    if (tid < 128) {
        int c=tid;
        float u,v; int ts;
        if (c==0){ u=1.f; v=p1*sq[TP(0)]; suf[TP(0)]=u; svf[TP(0)]=v; ts=1; }
        else     { u=sBf[c*2]; v=sBf[c*2+1]; ts=c*32; }
        int te=c*32+31;
        for (int t=ts;t<=te;t++){
            float qv=sq[TP(t)];
            float nu=fmaf(a10,v,a00*u);
            float nv=qv*fmaf(a11,v,a01*u);
            u=nu; v=nv;
            if ((t&7)==7){ float is=__fdividef(1.f,u+v); u*=is; v*=is; }
            suf[TP(t)]=u; svf[TP(t)]=v;
        }
    }
    __syncthreads();

    // backward replay; overwrite suf with gamma1
    if (tid < 128) {
        int c=tid;
        float u=sEb[c*2], v=sEb[c*2+1];
        int ts=c*32, te=c*32+31;
        {
            float n0=suf[TP(te)]*u, n1=svf[TP(te)]*v;
            suf[TP(te)] = __fdividef(n1, n0+n1);
        }
        for (int t=te-1;t>=ts;t--){
            float w=sq[TP(t+1)]*v;
            float nu=fmaf(a01,w,a00*u);
            float nv=fmaf(a11,w,a10*u);
            u=nu; v=nv;
            if ((t&7)==0){ float is=__fdividef(1.f,u+v); u*=is; v*=is; }
            float n0=suf[TP(t)]*u, n1=svf[TP(t)]*v;
            suf[TP(t)] = __fdividef(n1, n0+n1);
        }
    }
    __syncthreads();

    float* gmp = g_gm + (size_t)b*Tn;
#pragma unroll
    for (int t=tid; t<Tn; t+=256) gmp[t] = suf[TP(t)];
}

// ============== K3: epilogue — smem-staged coalesced I/O ==============
__global__ __launch_bounds__(256) void epi_kernel(
    const float* __restrict__ Qseq,
    const float* __restrict__ Wgp, const float* __restrict__ byp,
    float* __restrict__ out)
{
    __shared__ float sQ[2560];
    __shared__ float sG[1280];
    int tid = threadIdx.x;
    size_t base = (size_t)blockIdx.x*256;

    const float* Qb = Qseq + base*10;
#pragma unroll
    for (int i=tid;i<2560;i+=256) sQ[i]=Qb[i];

    float WG[20], BY[4];
#pragma unroll
    for (int i=0;i<20;i++) WG[i]=Wgp[i];
#pragma unroll
    for (int i=0;i<4;i++) BY[i]=byp[i];
    __syncthreads();

    size_t idx = base + tid;
    float gm1 = g_gm[idx], gm0 = 1.f - gm1;
    float lg0 = __logf(gm0), lg1 = __logf(gm1);

    unsigned hv = g_h[idx];
    __half2 h2 = *reinterpret_cast<__half2*>(&hv);
    float h0=__low2float(h2), h1=__high2float(h2);

    float gk[2][5];
#pragma unroll
    for (int k=0;k<2;k++){
        float wv[5], mx=-1e30f;
#pragma unroll
        for (int a=0;a<5;a++){ wv[a]=fmaf(h0,WG[k*10+a],h1*WG[k*10+5+a]); mx=fmaxf(mx,wv[a]); }
        float s=0.f;
#pragma unroll
        for (int a=0;a<5;a++){ wv[a]=__expf(wv[a]-mx); s+=wv[a]; }
        float is=__fdividef(1.f,s);
#pragma unroll
        for (int a=0;a<5;a++) gk[k][a]=wv[a]*is;
    }
    float gv[5];
#pragma unroll
    for (int a=0;a<5;a++) gv[a]=fmaf(gm0,gk[0][a],gm1*gk[1][a]);

    float V0=fmaf(gm0,BY[0],gm1*BY[2]);
    float V1=fmaf(gm0,BY[1],gm1*BY[3]);
#pragma unroll
    for (int a=0;a<5;a++){
        float qx=sQ[tid*10+a*2], qy=sQ[tid*10+a*2+1];
        V0=fmaf(gv[a],qx,V0);
        V1=fmaf(gv[a],qy,V1);
        sG[tid*5+a]=gv[a];
    }
    float mv=fmaxf(V0,V1);
    float lse=mv+__logf(__expf(V0-mv)+__expf(V1-mv));

    const size_t OFF1=(size_t)BT*2, OFF2=(size_t)BT*7;
    reinterpret_cast<float2*>(out)[idx]      = make_float2(V0-lse, V1-lse);
    reinterpret_cast<float2*>(out+OFF2)[idx] = make_float2(lg0, lg1);
    __syncthreads();
    float* go = out + OFF1 + base*5;
#pragma unroll
    for (int i=tid;i<1280;i+=256) go[i]=sG[i];
}

// ========================= launch =========================
extern "C" void kernel_launch(void* const* d_in, const int* in_sizes, int n_in,
                              void* d_out, int out_size)
{
    const float* x    =(const float*)d_in[0];
    const float* Qseq =(const float*)d_in[1];
    const float* lpi  =(const float*)d_in[2];
    const float* lA   =(const float*)d_in[3];
    const float* fc1w =(const float*)d_in[4];
    const float* fc1b =(const float*)d_in[5];
    const float* fc2w =(const float*)d_in[6];
    const float* fc2b =(const float*)d_in[7];
    const float* wih  =(const float*)d_in[8];
    const float* whh  =(const float*)d_in[9];
    const float* bih  =(const float*)d_in[10];
    const float* bhh  =(const float*)d_in[11];
    const float* Wg   =(const float*)d_in[12];
    const float* by   =(const float*)d_in[13];
    float* out=(float*)d_out;

    static bool init=false;
    if (!init){
        cudaFuncSetAttribute(hmm_kernel, cudaFuncAttributeMaxDynamicSharedMemorySize, HMM_SMEM);
        cudaFuncSetAttribute(gru_kernel, cudaFuncAttributeMaxDynamicSharedMemorySize, GRU_SMEM);
        init=true;
    }

    gru_kernel<<<512,256,GRU_SMEM>>>(x,wih,whh,bih,bhh);
    hmm_kernel<<<256,256,HMM_SMEM>>>(x,lpi,lA,fc1w,fc1b,fc2w,fc2b);
    epi_kernel<<<4096,256>>>(Qseq,Wg,by,out);
}

// round 10
// speedup vs baseline: 1.2499x; 1.2499x over previous
#include <cuda_runtime.h>
#include <cuda_fp16.h>
#include <cstdint>
#include <math.h>

#define Bn 256
#define Tn 4096
#define BT (Bn*Tn)

__device__ unsigned g_h[BT];   // GRU hidden half2

static __device__ __forceinline__ __half2 tanh2(__half2 x){
    unsigned xi = *reinterpret_cast<unsigned*>(&x), ri;
    asm("tanh.approx.f16x2 %0, %1;" : "=r"(ri) : "r"(xi));
    return *reinterpret_cast<__half2*>(&ri);
}
static __device__ __forceinline__ float tanhap(float x){
    float y; asm("tanh.approx.f32 %0, %1;" : "=f"(y) : "f"(x)); return y;
}

// ============== K1: GRU — inline gates, 2 halves/batch, chunk 8, warmup 16 ==============
#define G_SX   6336                       // words: 2064*3 + pads
#define G_HB   2176                       // words: 2048 + pads
#define GRU_SMEM ((G_SX+G_HB)*4)          // 34048 B

__global__ __launch_bounds__(256) void gru_kernel(
    const float* __restrict__ x,
    const float* __restrict__ wih, const float* __restrict__ whh,
    const float* __restrict__ bih, const float* __restrict__ bhh)
{
    extern __shared__ float sgru[];
    float*    sx = sgru;
    unsigned* hb = reinterpret_cast<unsigned*>(sgru + G_SX);

    int b    = blockIdx.x >> 1;
    int half = blockIdx.x & 1;
    int tid  = threadIdx.x;

    int off      = half ? 16 : 0;
    int tbase    = half*2048 - off;
    int tile_len = 2048 + off;

    // coalesced x -> padded smem
    const float* xb = x + (size_t)(b*Tn + tbase)*3;
    int nw = tile_len*3;
#pragma unroll
    for (int i = tid; i < nw; i += 256) {
        int t = i/3;
        sx[i + (t>>4)] = xb[i];
    }

    float WI[18], CB[6];
#pragma unroll
    for (int j=0;j<4;j++){
#pragma unroll
        for (int d=0;d<3;d++) WI[j*3+d] = 0.5f*wih[j*3+d];
        CB[j] = 0.5f*(bih[j]+bhh[j]);
    }
#pragma unroll
    for (int j=4;j<6;j++){
#pragma unroll
        for (int d=0;d<3;d++) WI[j*3+d] = wih[j*3+d];
        CB[j] = bih[j];
    }
    float w[12];
#pragma unroll
    for (int i=0;i<12;i++) w[i]=whh[i];
    __half2 WRA=__floats2half2_rn(0.5f*w[0],0.5f*w[2]), WRB=__floats2half2_rn(0.5f*w[1],0.5f*w[3]);
    __half2 WZA=__floats2half2_rn(0.5f*w[4],0.5f*w[6]), WZB=__floats2half2_rn(0.5f*w[5],0.5f*w[7]);
    __half2 WNA=__floats2half2_rn(w[8],w[10]),          WNB=__floats2half2_rn(w[9],w[11]);
    __half2 BN =__floats2half2_rn(bhh[4],bhh[5]);
    const __half2 H05=__floats2half2_rn(0.5f,0.5f), HM05=__floats2half2_rn(-0.5f,-0.5f);
    __syncthreads();

    // all 256 threads: chunk of 8 outputs, up to 16-step warmup
    int c = tid;
    int l0, nwarm;
    if (half == 0) {
        l0 = c*8 - 16; if (l0 < 0) l0 = 0;
        nwarm = c*8 - l0;                      // 0, 8, or 16 (exact for c<2)
    } else {
        l0 = c*8; nwarm = 16;
    }

    __half2 h = __floats2half2_rn(0.f,0.f);
#pragma unroll 4
    for (int s=0; s<24; s++){
        int l = l0 + s;
        int a = l*3 + (l>>4);
        float x0=sx[a], x1=sx[a+1], x2=sx[a+2];
        float gr0=fmaf(WI[0],x0,fmaf(WI[1],x1,fmaf(WI[2],x2,CB[0])));
        float gr1=fmaf(WI[3],x0,fmaf(WI[4],x1,fmaf(WI[5],x2,CB[1])));
        float gz0=fmaf(WI[6],x0,fmaf(WI[7],x1,fmaf(WI[8],x2,CB[2])));
        float gz1=fmaf(WI[9],x0,fmaf(WI[10],x1,fmaf(WI[11],x2,CB[3])));
        float gn0=fmaf(WI[12],x0,fmaf(WI[13],x1,fmaf(WI[14],x2,CB[4])));
        float gn1=fmaf(WI[15],x0,fmaf(WI[16],x1,fmaf(WI[17],x2,CB[5])));
        __half2 CR=__floats2half2_rn(gr0,gr1);
        __half2 CZ=__floats2half2_rn(gz0,gz1);
        __half2 CN=__floats2half2_rn(gn0,gn1);

        __half2 h0b=__half2half2(__low2half(h)), h1b=__half2half2(__high2half(h));
        __half2 aR=__hfma2(h0b,WRA,__hfma2(h1b,WRB,CR));
        __half2 aZ=__hfma2(h0b,WZA,__hfma2(h1b,WZB,CZ));
        __half2 GN=__hfma2(h0b,WNA,__hfma2(h1b,WNB,BN));
        __half2 tr=tanh2(aR), tz=tanh2(aZ);
        __half2 Ch=__hmul2(GN,H05);
        __half2 aN=__hfma2(tr,Ch,__hadd2(CN,Ch));
        __half2 tn=tanh2(aN);
        __half2 A =__hfma2(tz,HM05,H05);
        __half2 hh=__hmul2(h,H05);
        __half2 ZH=__hfma2(tz,hh,hh);
        h = __hfma2(tn,A,ZH);

        if (s>=nwarm && s<nwarm+8){
            int o = l - off;                  // 0..2047
            hb[o + (o>>4)] = *reinterpret_cast<unsigned*>(&h);
        }
    }
    __syncthreads();

    unsigned* hout = g_h + (size_t)b*Tn + half*2048;
#pragma unroll
    for (int u=tid; u<2048; u+=256) hout[u] = hb[u + (u>>4)];
}

// ============== K2: emitter + HMM scan + fused epilogue ==============
#define TP(t) ((t) + ((t)>>4))
#define HSQ   0
#define HSUF  4352
#define HSVF  8704
#define HSXE  13056
#define HSSUB 16128
#define HSP   17152
#define HSBF  17664
#define HSEB  17920
#define HMM_SMEM (18176*4)

__global__ __launch_bounds__(256) void hmm_kernel(
    const float* __restrict__ x,   const float* __restrict__ Qseq,
    const float* __restrict__ lpi, const float* __restrict__ lAg,
    const float* __restrict__ fc1w,const float* __restrict__ fc1b,
    const float* __restrict__ fc2w,const float* __restrict__ fc2b,
    const float* __restrict__ Wgp, const float* __restrict__ byp,
    float* __restrict__ out)
{
    extern __shared__ float sm[];
    float* sq   = sm + HSQ;
    float* suf  = sm + HSUF;
    float* svf  = sm + HSVF;
    float* sxe  = sm + HSXE;
    float* sSub = sm + HSSUB;
    float* sP   = sm + HSP;
    float* sBf  = sm + HSBF;
    float* sEb  = sm + HSEB;

    int b = blockIdx.x, tid = threadIdx.x;

    // ---- emitter -> q (4 coalesced sections) ----
    {
        float W1[24], B1[8], DW[8];
#pragma unroll
        for (int i=0;i<24;i++) W1[i]=fc1w[i];
#pragma unroll
        for (int i=0;i<8;i++){ B1[i]=fc1b[i]; DW[i]=fc2w[8+i]-fc2w[i]; }
        float db = fc2b[1]-fc2b[0];
        for (int sec=0; sec<4; sec++){
            const float* xb = x + ((size_t)b*Tn + sec*1024)*3;
            __syncthreads();
#pragma unroll
            for (int i=tid;i<3072;i+=256) sxe[i]=xb[i];
            __syncthreads();
#pragma unroll
            for (int j=0;j<4;j++){
                int tl = tid + j*256;
                float x0=sxe[tl*3], x1=sxe[tl*3+1], x2=sxe[tl*3+2];
                float d = db;
#pragma unroll
                for (int k=0;k<8;k++){
                    float u = fmaf(W1[k*3],x0,fmaf(W1[k*3+1],x1,fmaf(W1[k*3+2],x2,B1[k])));
                    d = fmaf(DW[k], tanhap(u), d);
                }
                int t = sec*1024 + tl;
                sq[TP(t)] = __expf(d);
            }
        }
    }

    float l00=lAg[0],l01=lAg[1],l10=lAg[2],l11=lAg[3];
    float m0=fmaxf(l00,l01), m1=fmaxf(l10,l11);
    float e00=__expf(l00-m0), e01=__expf(l01-m0), e10=__expf(l10-m1), e11=__expf(l11-m1);
    float i0=__fdividef(1.f,e00+e01), i1=__fdividef(1.f,e10+e11);
    float a00=e00*i0, a01=e01*i0, a10=e10*i1, a11=e11*i1;
    float p1=__expf(lpi[1]-lpi[0]);
    __syncthreads();

    // ---- 16-step sub-products ----
    {
        int ts = tid*16, te = ts+16;
        if (tid==0) ts = 1;
        float p00=1.f,p01=0.f,p10=0.f,p11=1.f;
        for (int t=ts;t<te;t++){
            float qv=sq[TP(t)], qa01=a01*qv, qa11=a11*qv;
            float n00=fmaf(p01,a10,p00*a00), n01=fmaf(p01,qa11,p00*qa01);
            float n10=fmaf(p11,a10,p10*a00), n11=fmaf(p11,qa11,p10*qa01);
            p00=n00;p01=n01;p10=n10;p11=n11;
        }
        float s=__fdividef(1.f,p00+p01+p10+p11);
        sSub[tid*4]=p00*s; sSub[tid*4+1]=p01*s; sSub[tid*4+2]=p10*s; sSub[tid*4+3]=p11*s;
    }
    __syncthreads();

    // ---- combine -> 128 chunk products ----
    if (tid < 128) {
        const float* S0 = sSub + tid*8;
        const float* S1 = S0 + 4;
        float p00=S0[0],p01=S0[1],p10=S0[2],p11=S0[3];
        float n00=fmaf(p01,S1[2],p00*S1[0]), n01=fmaf(p01,S1[3],p00*S1[1]);
        float n10=fmaf(p11,S1[2],p10*S1[0]), n11=fmaf(p11,S1[3],p10*S1[1]);
        float s=__fdividef(1.f,n00+n01+n10+n11);
        sP[tid*4]=n00*s; sP[tid*4+1]=n01*s; sP[tid*4+2]=n10*s; sP[tid*4+3]=n11*s;
    }
    __syncthreads();

    // ---- boundary chains ----
    if (tid == 0) {
        float u=1.f, v=p1*sq[TP(0)];
        sBf[0]=u; sBf[1]=v;
        for (int c=0;c<127;c++){
            const float* P=sP+c*4;
            float nu=fmaf(v,P[2],u*P[0]);
            float nv=fmaf(v,P[3],u*P[1]);
            u=nu; v=nv;
            if ((c&7)==7){ float is=__fdividef(1.f,u+v); u*=is; v*=is; }
            sBf[(c+1)*2]=u; sBf[(c+1)*2+1]=v;
        }
    } else if (tid == 32) {
        float u=1.f, v=1.f;
        sEb[127*2]=1.f; sEb[127*2+1]=1.f;
        for (int c=126;c>=0;c--){
            const float* P=sP+(c+1)*4;
            float nu=fmaf(P[1],v,P[0]*u);
            float nv=fmaf(P[3],v,P[2]*u);
            u=nu; v=nv;
            if ((c&7)==0){ float is=__fdividef(1.f,u+v); u*=is; v*=is; }
            sEb[c*2]=u; sEb[c*2+1]=v;
        }
    }
    __syncthreads();

    // ---- forward replay ----
    if (tid < 128) {
        int c=tid;
        float u,v; int ts;
        if (c==0){ u=1.f; v=p1*sq[TP(0)]; suf[TP(0)]=u; svf[TP(0)]=v; ts=1; }
        else     { u=sBf[c*2]; v=sBf[c*2+1]; ts=c*32; }
        int te=c*32+31;
        for (int t=ts;t<=te;t++){
            float qv=sq[TP(t)];
            float nu=fmaf(a10,v,a00*u);
            float nv=qv*fmaf(a11,v,a01*u);
            u=nu; v=nv;
            if ((t&7)==7){ float is=__fdividef(1.f,u+v); u*=is; v*=is; }
            suf[TP(t)]=u; svf[TP(t)]=v;
        }
    }
    __syncthreads();

    // ---- backward replay; suf <- gamma1 ----
    if (tid < 128) {
        int c=tid;
        float u=sEb[c*2], v=sEb[c*2+1];
        int ts=c*32, te=c*32+31;
        {
            float n0=suf[TP(te)]*u, n1=svf[TP(te)]*v;
            suf[TP(te)] = __fdividef(n1, n0+n1);
        }
        for (int t=te-1;t>=ts;t--){
            float w=sq[TP(t+1)]*v;
            float nu=fmaf(a01,w,a00*u);
            float nv=fmaf(a11,w,a10*u);
            u=nu; v=nv;
            if ((t&7)==0){ float is=__fdividef(1.f,u+v); u*=is; v*=is; }
            float n0=suf[TP(t)]*u, n1=svf[TP(t)]*v;
            suf[TP(t)] = __fdividef(n1, n0+n1);
        }
    }

    // ---- fused epilogue: 16 tiles of 256 t (svf reused as g-stage) ----
    float WG[20], BY[4];
#pragma unroll
    for (int i=0;i<20;i++) WG[i]=Wgp[i];
#pragma unroll
    for (int i=0;i<4;i++) BY[i]=byp[i];

    const size_t OFF1=(size_t)BT*2, OFF2=(size_t)BT*7;
    float* sG = svf;   // 1280 words used per tile
    for (int tile=0; tile<16; tile++){
        size_t base = (size_t)b*Tn + tile*256;
        __syncthreads();
        // stage Q tile (float4, coalesced)
        const float4* Qb = reinterpret_cast<const float4*>(Qseq + base*10);
        float4* sQ4 = reinterpret_cast<float4*>(sxe);
#pragma unroll
        for (int i=tid;i<640;i+=256) sQ4[i]=Qb[i];
        __syncthreads();

        int tl = tile*256 + tid;
        float gm1 = suf[TP(tl)], gm0 = 1.f - gm1;
        float lg0 = __logf(gm0), lg1 = __logf(gm1);

        unsigned hv = g_h[base + tid];
        __half2 h2 = *reinterpret_cast<__half2*>(&hv);
        float h0=__low2float(h2), h1=__high2float(h2);

        float gk[2][5];
#pragma unroll
        for (int k=0;k<2;k++){
            float wv[5], mx=-1e30f;
#pragma unroll
            for (int a=0;a<5;a++){ wv[a]=fmaf(h0,WG[k*10+a],h1*WG[k*10+5+a]); mx=fmaxf(mx,wv[a]); }
            float s=0.f;
#pragma unroll
            for (int a=0;a<5;a++){ wv[a]=__expf(wv[a]-mx); s+=wv[a]; }
            float is=__fdividef(1.f,s);
#pragma unroll
            for (int a=0;a<5;a++) gk[k][a]=wv[a]*is;
        }
        float gv[5];
#pragma unroll
        for (int a=0;a<5;a++) gv[a]=fmaf(gm0,gk[0][a],gm1*gk[1][a]);

        float V0=fmaf(gm0,BY[0],gm1*BY[2]);
        float V1=fmaf(gm0,BY[1],gm1*BY[3]);
#pragma unroll
        for (int a=0;a<5;a++){
            float qx=sxe[tid*10+a*2], qy=sxe[tid*10+a*2+1];
            V0=fmaf(gv[a],qx,V0);
            V1=fmaf(gv[a],qy,V1);
            sG[tid*5+a]=gv[a];
        }
        float mv=fmaxf(V0,V1);
        float lse=mv+__logf(__expf(V0-mv)+__expf(V1-mv));

        reinterpret_cast<float2*>(out)[base + tid]      = make_float2(V0-lse, V1-lse);
        reinterpret_cast<float2*>(out+OFF2)[base + tid] = make_float2(lg0, lg1);
        __syncthreads();
        float* go = out + OFF1 + base*5;
#pragma unroll
        for (int i=tid;i<1280;i+=256) go[i]=sG[i];
    }
}

// ========================= launch =========================
extern "C" void kernel_launch(void* const* d_in, const int* in_sizes, int n_in,
                              void* d_out, int out_size)
{
    const float* x    =(const float*)d_in[0];
    const float* Qseq =(const float*)d_in[1];
    const float* lpi  =(const float*)d_in[2];
    const float* lA   =(const float*)d_in[3];
    const float* fc1w =(const float*)d_in[4];
    const float* fc1b =(const float*)d_in[5];
    const float* fc2w =(const float*)d_in[6];
    const float* fc2b =(const float*)d_in[7];
    const float* wih  =(const float*)d_in[8];
    const float* whh  =(const float*)d_in[9];
    const float* bih  =(const float*)d_in[10];
    const float* bhh  =(const float*)d_in[11];
    const float* Wg   =(const float*)d_in[12];
    const float* by   =(const float*)d_in[13];
    float* out=(float*)d_out;

    static bool init=false;
    if (!init){
        cudaFuncSetAttribute(hmm_kernel, cudaFuncAttributeMaxDynamicSharedMemorySize, HMM_SMEM);
        cudaFuncSetAttribute(gru_kernel, cudaFuncAttributeMaxDynamicSharedMemorySize, GRU_SMEM);
        init=true;
    }

    gru_kernel<<<512,256,GRU_SMEM>>>(x,wih,whh,bih,bhh);
    hmm_kernel<<<256,256,HMM_SMEM>>>(x,Qseq,lpi,lA,fc1w,fc1b,fc2w,fc2b,Wg,by,out);
}

// round 11
// speedup vs baseline: 1.4174x; 1.1340x over previous
#include <cuda_runtime.h>
#include <cuda_fp16.h>
#include <cstdint>
#include <math.h>

#define Bn 256
#define Tn 4096
#define BT (Bn*Tn)

__device__ unsigned g_h [BT];   // GRU hidden half2
__device__ float    g_gm[BT];   // gamma_1

static __device__ __forceinline__ __half2 tanh2(__half2 x){
    unsigned xi = *reinterpret_cast<unsigned*>(&x), ri;
    asm("tanh.approx.f16x2 %0, %1;" : "=r"(ri) : "r"(xi));
    return *reinterpret_cast<__half2*>(&ri);
}
static __device__ __forceinline__ float tanhap(float x){
    float y; asm("tanh.approx.f32 %0, %1;" : "=f"(y) : "f"(x)); return y;
}

// ============== K1: GRU — inline gates, 2 halves/batch, chunk 8, warmup 16 ==============
#define G_SX   6336                       // words: 2064*3 + pads
#define G_HB   2176                       // words: 2048 + pads
#define GRU_SMEM ((G_SX+G_HB)*4)          // 34048 B

__global__ __launch_bounds__(256) void gru_kernel(
    const float* __restrict__ x,
    const float* __restrict__ wih, const float* __restrict__ whh,
    const float* __restrict__ bih, const float* __restrict__ bhh)
{
    extern __shared__ float sgru[];
    float*    sx = sgru;
    unsigned* hb = reinterpret_cast<unsigned*>(sgru + G_SX);

    int b    = blockIdx.x >> 1;
    int half = blockIdx.x & 1;
    int tid  = threadIdx.x;

    int off      = half ? 16 : 0;
    int tbase    = half*2048 - off;
    int tile_len = 2048 + off;

    const float* xb = x + (size_t)(b*Tn + tbase)*3;
    int nw = tile_len*3;
#pragma unroll
    for (int i = tid; i < nw; i += 256) {
        int t = i/3;
        sx[i + (t>>4)] = xb[i];
    }

    float WI[18], CB[6];
#pragma unroll
    for (int j=0;j<4;j++){
#pragma unroll
        for (int d=0;d<3;d++) WI[j*3+d] = 0.5f*wih[j*3+d];
        CB[j] = 0.5f*(bih[j]+bhh[j]);
    }
#pragma unroll
    for (int j=4;j<6;j++){
#pragma unroll
        for (int d=0;d<3;d++) WI[j*3+d] = wih[j*3+d];
        CB[j] = bih[j];
    }
    float w[12];
#pragma unroll
    for (int i=0;i<12;i++) w[i]=whh[i];
    __half2 WRA=__floats2half2_rn(0.5f*w[0],0.5f*w[2]), WRB=__floats2half2_rn(0.5f*w[1],0.5f*w[3]);
    __half2 WZA=__floats2half2_rn(0.5f*w[4],0.5f*w[6]), WZB=__floats2half2_rn(0.5f*w[5],0.5f*w[7]);
    __half2 WNA=__floats2half2_rn(w[8],w[10]),          WNB=__floats2half2_rn(w[9],w[11]);
    __half2 BN =__floats2half2_rn(bhh[4],bhh[5]);
    const __half2 H05=__floats2half2_rn(0.5f,0.5f), HM05=__floats2half2_rn(-0.5f,-0.5f);
    __syncthreads();

    int c = tid;
    int l0, nwarm;
    if (half == 0) {
        l0 = c*8 - 16; if (l0 < 0) l0 = 0;
        nwarm = c*8 - l0;
    } else {
        l0 = c*8; nwarm = 16;
    }

    __half2 h = __floats2half2_rn(0.f,0.f);
#pragma unroll 4
    for (int s=0; s<24; s++){
        int l = l0 + s;
        int a = l*3 + (l>>4);
        float x0=sx[a], x1=sx[a+1], x2=sx[a+2];
        float gr0=fmaf(WI[0],x0,fmaf(WI[1],x1,fmaf(WI[2],x2,CB[0])));
        float gr1=fmaf(WI[3],x0,fmaf(WI[4],x1,fmaf(WI[5],x2,CB[1])));
        float gz0=fmaf(WI[6],x0,fmaf(WI[7],x1,fmaf(WI[8],x2,CB[2])));
        float gz1=fmaf(WI[9],x0,fmaf(WI[10],x1,fmaf(WI[11],x2,CB[3])));
        float gn0=fmaf(WI[12],x0,fmaf(WI[13],x1,fmaf(WI[14],x2,CB[4])));
        float gn1=fmaf(WI[15],x0,fmaf(WI[16],x1,fmaf(WI[17],x2,CB[5])));
        __half2 CR=__floats2half2_rn(gr0,gr1);
        __half2 CZ=__floats2half2_rn(gz0,gz1);
        __half2 CN=__floats2half2_rn(gn0,gn1);

        __half2 h0b=__half2half2(__low2half(h)), h1b=__half2half2(__high2half(h));
        __half2 aR=__hfma2(h0b,WRA,__hfma2(h1b,WRB,CR));
        __half2 aZ=__hfma2(h0b,WZA,__hfma2(h1b,WZB,CZ));
        __half2 GN=__hfma2(h0b,WNA,__hfma2(h1b,WNB,BN));
        __half2 tr=tanh2(aR), tz=tanh2(aZ);
        __half2 Ch=__hmul2(GN,H05);
        __half2 aN=__hfma2(tr,Ch,__hadd2(CN,Ch));
        __half2 tn=tanh2(aN);
        __half2 A =__hfma2(tz,HM05,H05);
        __half2 hh=__hmul2(h,H05);
        __half2 ZH=__hfma2(tz,hh,hh);
        h = __hfma2(tn,A,ZH);

        if (s>=nwarm && s<nwarm+8){
            int o = l - off;
            hb[o + (o>>4)] = *reinterpret_cast<unsigned*>(&h);
        }
    }
    __syncthreads();

    unsigned* hout = g_h + (size_t)b*Tn + half*2048;
#pragma unroll
    for (int u=tid; u<2048; u+=256) hout[u] = hb[u + (u>>4)];
}

// ============== K2: emitter + HMM scan -> gamma1 ==============
#define TP(t) ((t) + ((t)>>4))
#define HSQ   0
#define HSUF  4352
#define HSVF  8704
#define HSXE  13056
#define HSSUB 16128
#define HSP   17152
#define HSBF  17664
#define HSEB  17920
#define HMM_SMEM (18176*4)

__global__ __launch_bounds__(256) void hmm_kernel(
    const float* __restrict__ x,
    const float* __restrict__ lpi, const float* __restrict__ lAg,
    const float* __restrict__ fc1w,const float* __restrict__ fc1b,
    const float* __restrict__ fc2w,const float* __restrict__ fc2b)
{
    extern __shared__ float sm[];
    float* sq   = sm + HSQ;
    float* suf  = sm + HSUF;
    float* svf  = sm + HSVF;
    float* sxe  = sm + HSXE;
    float* sSub = sm + HSSUB;
    float* sP   = sm + HSP;
    float* sBf  = sm + HSBF;
    float* sEb  = sm + HSEB;

    int b = blockIdx.x, tid = threadIdx.x;

    float W1[24], B1[8], DW[8];
#pragma unroll
    for (int i=0;i<24;i++) W1[i]=fc1w[i];
#pragma unroll
    for (int i=0;i<8;i++){ B1[i]=fc1b[i]; DW[i]=fc2w[8+i]-fc2w[i]; }
    float db = fc2b[1]-fc2b[0];

    for (int sec=0; sec<4; sec++){
        const float* xb = x + ((size_t)b*Tn + sec*1024)*3;
        __syncthreads();
#pragma unroll
        for (int i=tid;i<3072;i+=256) sxe[i]=xb[i];
        __syncthreads();
#pragma unroll
        for (int j=0;j<4;j++){
            int tl = tid + j*256;
            float x0=sxe[tl*3], x1=sxe[tl*3+1], x2=sxe[tl*3+2];
            float d = db;
#pragma unroll
            for (int k=0;k<8;k++){
                float u = fmaf(W1[k*3],x0,fmaf(W1[k*3+1],x1,fmaf(W1[k*3+2],x2,B1[k])));
                d = fmaf(DW[k], tanhap(u), d);
            }
            int t = sec*1024 + tl;
            sq[TP(t)] = __expf(d);
        }
    }

    float l00=lAg[0],l01=lAg[1],l10=lAg[2],l11=lAg[3];
    float m0=fmaxf(l00,l01), m1=fmaxf(l10,l11);
    float e00=__expf(l00-m0), e01=__expf(l01-m0), e10=__expf(l10-m1), e11=__expf(l11-m1);
    float i0=__fdividef(1.f,e00+e01), i1=__fdividef(1.f,e10+e11);
    float a00=e00*i0, a01=e01*i0, a10=e10*i1, a11=e11*i1;
    float p1=__expf(lpi[1]-lpi[0]);
    __syncthreads();

    // 16-step sub-products
    {
        int ts = tid*16, te = ts+16;
        if (tid==0) ts = 1;
        float p00=1.f,p01=0.f,p10=0.f,p11=1.f;
        for (int t=ts;t<te;t++){
            float qv=sq[TP(t)], qa01=a01*qv, qa11=a11*qv;
            float n00=fmaf(p01,a10,p00*a00), n01=fmaf(p01,qa11,p00*qa01);
            float n10=fmaf(p11,a10,p10*a00), n11=fmaf(p11,qa11,p10*qa01);
            p00=n00;p01=n01;p10=n10;p11=n11;
        }
        float s=__fdividef(1.f,p00+p01+p10+p11);
        sSub[tid*4]=p00*s; sSub[tid*4+1]=p01*s; sSub[tid*4+2]=p10*s; sSub[tid*4+3]=p11*s;
    }
    __syncthreads();

    // combine -> 128 chunk products (32 t each)
    if (tid < 128) {
        const float* S0 = sSub + tid*8;
        const float* S1 = S0 + 4;
        float p00=S0[0],p01=S0[1],p10=S0[2],p11=S0[3];
        float n00=fmaf(p01,S1[2],p00*S1[0]), n01=fmaf(p01,S1[3],p00*S1[1]);
        float n10=fmaf(p11,S1[2],p10*S1[0]), n11=fmaf(p11,S1[3],p10*S1[1]);
        float s=__fdividef(1.f,n00+n01+n10+n11);
        sP[tid*4]=n00*s; sP[tid*4+1]=n01*s; sP[tid*4+2]=n10*s; sP[tid*4+3]=n11*s;
    }
    __syncthreads();

    // boundary chains
    if (tid == 0) {
        float u=1.f, v=p1*sq[TP(0)];
        sBf[0]=u; sBf[1]=v;
        for (int c=0;c<127;c++){
            const float* P=sP+c*4;
            float nu=fmaf(v,P[2],u*P[0]);
            float nv=fmaf(v,P[3],u*P[1]);
            u=nu; v=nv;
            if ((c&7)==7){ float is=__fdividef(1.f,u+v); u*=is; v*=is; }
            sBf[(c+1)*2]=u; sBf[(c+1)*2+1]=v;
        }
    } else if (tid == 32) {
        float u=1.f, v=1.f;
        sEb[127*2]=1.f; sEb[127*2+1]=1.f;
        for (int c=126;c>=0;c--){
            const float* P=sP+(c+1)*4;
            float nu=fmaf(P[1],v,P[0]*u);
            float nv=fmaf(P[3],v,P[2]*u);
            u=nu; v=nv;
            if ((c&7)==0){ float is=__fdividef(1.f,u+v); u*=is; v*=is; }
            sEb[c*2]=u; sEb[c*2+1]=v;
        }
    }
    __syncthreads();

    // forward replay
    if (tid < 128) {
        int c=tid;
        float u,v; int ts;
        if (c==0){ u=1.f; v=p1*sq[TP(0)]; suf[TP(0)]=u; svf[TP(0)]=v; ts=1; }
        else     { u=sBf[c*2]; v=sBf[c*2+1]; ts=c*32; }
        int te=c*32+31;
        for (int t=ts;t<=te;t++){
            float qv=sq[TP(t)];
            float nu=fmaf(a10,v,a00*u);
            float nv=qv*fmaf(a11,v,a01*u);
            u=nu; v=nv;
            if ((t&7)==7){ float is=__fdividef(1.f,u+v); u*=is; v*=is; }
            suf[TP(t)]=u; svf[TP(t)]=v;
        }
    }
    __syncthreads();

    // backward replay; overwrite suf with gamma1
    if (tid < 128) {
        int c=tid;
        float u=sEb[c*2], v=sEb[c*2+1];
        int ts=c*32, te=c*32+31;
        {
            float n0=suf[TP(te)]*u, n1=svf[TP(te)]*v;
            suf[TP(te)] = __fdividef(n1, n0+n1);
        }
        for (int t=te-1;t>=ts;t--){
            float w=sq[TP(t+1)]*v;
            float nu=fmaf(a01,w,a00*u);
            float nv=fmaf(a11,w,a10*u);
            u=nu; v=nv;
            if ((t&7)==0){ float is=__fdividef(1.f,u+v); u*=is; v*=is; }
            float n0=suf[TP(t)]*u, n1=svf[TP(t)]*v;
            suf[TP(t)] = __fdividef(n1, n0+n1);
        }
    }
    __syncthreads();

    float* gmp = g_gm + (size_t)b*Tn;
#pragma unroll
    for (int t=tid; t<Tn; t+=256) gmp[t] = suf[TP(t)];
}

// ============== K3: epilogue — smem-staged coalesced I/O, grid 4096 ==============
__global__ __launch_bounds__(256) void epi_kernel(
    const float* __restrict__ Qseq,
    const float* __restrict__ Wgp, const float* __restrict__ byp,
    float* __restrict__ out)
{
    __shared__ float sQ[2560];
    __shared__ float sG[1280];
    int tid = threadIdx.x;
    size_t base = (size_t)blockIdx.x*256;

    const float* Qb = Qseq + base*10;
#pragma unroll
    for (int i=tid;i<2560;i+=256) sQ[i]=Qb[i];

    float WG[20], BY[4];
#pragma unroll
    for (int i=0;i<20;i++) WG[i]=Wgp[i];
#pragma unroll
    for (int i=0;i<4;i++) BY[i]=byp[i];
    __syncthreads();

    size_t idx = base + tid;
    float gm1 = g_gm[idx], gm0 = 1.f - gm1;
    float lg0 = __logf(gm0), lg1 = __logf(gm1);

    unsigned hv = g_h[idx];
    __half2 h2 = *reinterpret_cast<__half2*>(&hv);
    float h0=__low2float(h2), h1=__high2float(h2);

    float gk[2][5];
#pragma unroll
    for (int k=0;k<2;k++){
        float wv[5], mx=-1e30f;
#pragma unroll
        for (int a=0;a<5;a++){ wv[a]=fmaf(h0,WG[k*10+a],h1*WG[k*10+5+a]); mx=fmaxf(mx,wv[a]); }
        float s=0.f;
#pragma unroll
        for (int a=0;a<5;a++){ wv[a]=__expf(wv[a]-mx); s+=wv[a]; }
        float is=__fdividef(1.f,s);
#pragma unroll
        for (int a=0;a<5;a++) gk[k][a]=wv[a]*is;
    }
    float gv[5];
#pragma unroll
    for (int a=0;a<5;a++) gv[a]=fmaf(gm0,gk[0][a],gm1*gk[1][a]);

    float V0=fmaf(gm0,BY[0],gm1*BY[2]);
    float V1=fmaf(gm0,BY[1],gm1*BY[3]);
#pragma unroll
    for (int a=0;a<5;a++){
        float qx=sQ[tid*10+a*2], qy=sQ[tid*10+a*2+1];
        V0=fmaf(gv[a],qx,V0);
        V1=fmaf(gv[a],qy,V1);
        sG[tid*5+a]=gv[a];
    }
    float mv=fmaxf(V0,V1);
    float lse=mv+__logf(__expf(V0-mv)+__expf(V1-mv));

    const size_t OFF1=(size_t)BT*2, OFF2=(size_t)BT*7;
    reinterpret_cast<float2*>(out)[idx]      = make_float2(V0-lse, V1-lse);
    reinterpret_cast<float2*>(out+OFF2)[idx] = make_float2(lg0, lg1);
    __syncthreads();
    float* go = out + OFF1 + base*5;
#pragma unroll
    for (int i=tid;i<1280;i+=256) go[i]=sG[i];
}

// ========================= launch =========================
extern "C" void kernel_launch(void* const* d_in, const int* in_sizes, int n_in,
                              void* d_out, int out_size)
{
    const float* x    =(const float*)d_in[0];
    const float* Qseq =(const float*)d_in[1];
    const float* lpi  =(const float*)d_in[2];
    const float* lA   =(const float*)d_in[3];
    const float* fc1w =(const float*)d_in[4];
    const float* fc1b =(const float*)d_in[5];
    const float* fc2w =(const float*)d_in[6];
    const float* fc2b =(const float*)d_in[7];
    const float* wih  =(const float*)d_in[8];
    const float* whh  =(const float*)d_in[9];
    const float* bih  =(const float*)d_in[10];
    const float* bhh  =(const float*)d_in[11];
    const float* Wg   =(const float*)d_in[12];
    const float* by   =(const float*)d_in[13];
    float* out=(float*)d_out;

    static bool init=false;
    if (!init){
        cudaFuncSetAttribute(hmm_kernel, cudaFuncAttributeMaxDynamicSharedMemorySize, HMM_SMEM);
        cudaFuncSetAttribute(gru_kernel, cudaFuncAttributeMaxDynamicSharedMemorySize, GRU_SMEM);
        init=true;
    }

    gru_kernel<<<512,256,GRU_SMEM>>>(x,wih,whh,bih,bhh);
    hmm_kernel<<<256,256,HMM_SMEM>>>(x,lpi,lA,fc1w,fc1b,fc2w,fc2b);
    epi_kernel<<<4096,256>>>(Qseq,Wg,by,out);
}